// round 1
// baseline (speedup 1.0000x reference)
#include <cuda_runtime.h>
#include <math.h>

// Problem constants (shapes fixed by setup_inputs)
#define C_DIM   20
#define HW      524288      // 512*1024
#define HW4     131072      // HW/4
#define HW4_SH  17          // log2(HW4)
#define BLK     256
#define PIX4_PER_THREAD 1   // each thread = one float4 = 4 pixels

// Normalized prototypes [m][c] followed by per-row squared norms psqn[m]
__device__ float g_proto[C_DIM * C_DIM + C_DIM];

__device__ __forceinline__ float sqrt_approx(float v) {
    float r; asm("sqrt.approx.f32 %0, %1;" : "=f"(r) : "f"(v)); return r;
}
__device__ __forceinline__ float rcp_approx(float v) {
    float r; asm("rcp.approx.f32 %0, %1;" : "=f"(r) : "f"(v)); return r;
}

// ---------------------------------------------------------------------------
// Prep: normalize prototype rows (dim=1), store normalized rows + their
// squared norms into g_proto. 20 rows -> 32 threads, one row per thread.
// ---------------------------------------------------------------------------
__global__ void proto_prep_kernel(const float* __restrict__ protos) {
    int m = threadIdx.x;
    if (m < C_DIM) {
        float v[C_DIM];
        float sq = 0.f;
        #pragma unroll
        for (int c = 0; c < C_DIM; c++) {
            v[c] = protos[m * C_DIM + c];
            sq = fmaf(v[c], v[c], sq);
        }
        float nrm = fmaxf(sqrtf(sq), 1e-12f);
        float inv = 1.0f / nrm;
        float s = 0.f;
        #pragma unroll
        for (int c = 0; c < C_DIM; c++) {
            float pv = v[c] * inv;
            g_proto[m * C_DIM + c] = pv;
            s = fmaf(pv, pv, s);
        }
        g_proto[C_DIM * C_DIM + m] = s;
    }
}

// ---------------------------------------------------------------------------
// Main kernel: each thread processes 4 consecutive pixels (one float4 along W).
//   input  idx: b*C*HW + c*HW + hw   (float4 units: base4 + c*HW4)
//   output idx: b*C*HW + m*HW + hw   (float4 units: base4 + m*HW4)
// ---------------------------------------------------------------------------
__global__ __launch_bounds__(BLK, 2)
void isomax_dist_kernel(const float* __restrict__ in,
                        const float* __restrict__ scale_p,
                        float* __restrict__ out) {
    __shared__ float sp[C_DIM * C_DIM + C_DIM];
    for (int i = threadIdx.x; i < C_DIM * C_DIM + C_DIM; i += BLK)
        sp[i] = g_proto[i];
    __syncthreads();

    const float sneg = -fabsf(__ldg(scale_p));   // logits = -|scale| * dist

    const float4* __restrict__ in4  = (const float4*)in;
    float4*       __restrict__ out4 = (float4*)out;

    unsigned q   = blockIdx.x * BLK + threadIdx.x;   // global float4-pixel index
    unsigned b   = q >> HW4_SH;
    unsigned rem = q & (HW4 - 1u);
    unsigned base4 = b * (C_DIM * HW4) + rem;

    // Load the 20-channel vectors for 4 pixels (20 x LDG.128, deep MLP)
    float4 x[C_DIM];
    #pragma unroll
    for (int c = 0; c < C_DIM; c++)
        x[c] = in4[base4 + (unsigned)c * HW4];

    // Squared norms per pixel
    float4 xsq = make_float4(0.f, 0.f, 0.f, 0.f);
    #pragma unroll
    for (int c = 0; c < C_DIM; c++) {
        xsq.x = fmaf(x[c].x, x[c].x, xsq.x);
        xsq.y = fmaf(x[c].y, x[c].y, xsq.y);
        xsq.z = fmaf(x[c].z, x[c].z, xsq.z);
        xsq.w = fmaf(x[c].w, x[c].w, xsq.w);
    }

    // inv = 1 / max(||x||, eps); xsqn = ||x_hat||^2 ; n2i = -2*inv
    float invx = rcp_approx(fmaxf(sqrt_approx(xsq.x), 1e-12f));
    float invy = rcp_approx(fmaxf(sqrt_approx(xsq.y), 1e-12f));
    float invz = rcp_approx(fmaxf(sqrt_approx(xsq.z), 1e-12f));
    float invw = rcp_approx(fmaxf(sqrt_approx(xsq.w), 1e-12f));
    float xnx = xsq.x * invx * invx;
    float xny = xsq.y * invy * invy;
    float xnz = xsq.z * invz * invz;
    float xnw = xsq.w * invw * invw;
    float n2ix = -2.f * invx, n2iy = -2.f * invy;
    float n2iz = -2.f * invz, n2iw = -2.f * invw;

    #pragma unroll 1
    for (int m = 0; m < C_DIM; m++) {
        const float4* pr = (const float4*)&sp[m * C_DIM];  // 80B rows, 16B aligned
        float4 dot = make_float4(0.f, 0.f, 0.f, 0.f);
        #pragma unroll
        for (int c4 = 0; c4 < C_DIM / 4; c4++) {
            float4 p = pr[c4];
            const float4 a0 = x[4 * c4 + 0];
            const float4 a1 = x[4 * c4 + 1];
            const float4 a2 = x[4 * c4 + 2];
            const float4 a3 = x[4 * c4 + 3];
            dot.x = fmaf(a0.x, p.x, dot.x); dot.x = fmaf(a1.x, p.y, dot.x);
            dot.x = fmaf(a2.x, p.z, dot.x); dot.x = fmaf(a3.x, p.w, dot.x);
            dot.y = fmaf(a0.y, p.x, dot.y); dot.y = fmaf(a1.y, p.y, dot.y);
            dot.y = fmaf(a2.y, p.z, dot.y); dot.y = fmaf(a3.y, p.w, dot.y);
            dot.z = fmaf(a0.z, p.x, dot.z); dot.z = fmaf(a1.z, p.y, dot.z);
            dot.z = fmaf(a2.z, p.z, dot.z); dot.z = fmaf(a3.z, p.w, dot.z);
            dot.w = fmaf(a0.w, p.x, dot.w); dot.w = fmaf(a1.w, p.y, dot.w);
            dot.w = fmaf(a2.w, p.z, dot.w); dot.w = fmaf(a3.w, p.w, dot.w);
        }
        float psn = sp[C_DIM * C_DIM + m];

        float d2x = fmaf(dot.x, n2ix, xnx + psn);
        float d2y = fmaf(dot.y, n2iy, xny + psn);
        float d2z = fmaf(dot.z, n2iz, xnz + psn);
        float d2w = fmaf(dot.w, n2iw, xnw + psn);
        d2x = fmaxf(d2x, 0.f); d2y = fmaxf(d2y, 0.f);
        d2z = fmaxf(d2z, 0.f); d2w = fmaxf(d2w, 0.f);

        float4 o;
        o.x = sneg * sqrt_approx(d2x);
        o.y = sneg * sqrt_approx(d2y);
        o.z = sneg * sqrt_approx(d2z);
        o.w = sneg * sqrt_approx(d2w);
        out4[base4 + (unsigned)m * HW4] = o;
    }
}

extern "C" void kernel_launch(void* const* d_in, const int* in_sizes, int n_in,
                              void* d_out, int out_size) {
    const float* features = (const float*)d_in[0];  // [8,20,512,1024] f32
    const float* protos   = (const float*)d_in[1];  // [20,20] f32
    const float* dscale   = (const float*)d_in[2];  // [1] f32

    proto_prep_kernel<<<1, 32>>>(protos);

    // total pixels = in_sizes[0] / C ; float4 threads = pixels/4
    int n_pix4 = (in_sizes[0] / C_DIM) / 4;
    int grid = (n_pix4 + BLK - 1) / BLK;
    isomax_dist_kernel<<<grid, BLK>>>(features, dscale, (float*)d_out);
}